// round 1
// baseline (speedup 1.0000x reference)
#include <cuda_runtime.h>
#include <math.h>

#define B_  2
#define S_  2048
#define D_  1024
#define H_  16
#define HD_ 64

// Scratch (allocation-free rule: __device__ globals)
__device__ float g_qkv[(size_t)B_ * S_ * 3 * D_];  // [B, S, 3D] output of QKV GEMM
__device__ float g_ctx[(size_t)B_ * S_ * D_];      // [B, S, D] attention context

// ---------------------------------------------------------------------------
// SGEMM + bias: C[M,N] = A[M,K] @ B[K,N] + bias[N]
// 128x128 block tile, BK=8, 256 threads, 8x8 per-thread micro-tile.
// M,N,K all multiples of 128/8 here, so no bounds checks.
// ---------------------------------------------------------------------------
__global__ __launch_bounds__(256)
void sgemm_bias(const float* __restrict__ A, const float* __restrict__ Bm,
                const float* __restrict__ bias, float* __restrict__ C,
                int M, int N, int K) {
    const int BK = 8;
    __shared__ float As[BK][128];   // A tile transposed: As[k][m]
    __shared__ float Bs[BK][128];   // B tile: Bs[k][n]

    int tid  = threadIdx.x;
    int brow = blockIdx.y * 128;
    int bcol = blockIdx.x * 128;

    int arow = tid >> 1;            // 0..127
    int acol = (tid & 1) << 2;      // 0 or 4
    int brl  = tid >> 5;            // 0..7
    int bcl  = (tid & 31) << 2;     // 0..124

    int ty = tid >> 4;              // 0..15
    int tx = tid & 15;              // 0..15

    float acc[8][8];
#pragma unroll
    for (int i = 0; i < 8; i++)
#pragma unroll
        for (int j = 0; j < 8; j++) acc[i][j] = 0.f;

    for (int k0 = 0; k0 < K; k0 += BK) {
        float4 av = *(const float4*)(A + (size_t)(brow + arow) * K + k0 + acol);
        As[acol + 0][arow] = av.x;
        As[acol + 1][arow] = av.y;
        As[acol + 2][arow] = av.z;
        As[acol + 3][arow] = av.w;
        *(float4*)&Bs[brl][bcl] =
            *(const float4*)(Bm + (size_t)(k0 + brl) * N + bcol + bcl);
        __syncthreads();

#pragma unroll
        for (int kk = 0; kk < BK; kk++) {
            float ra[8], rb[8];
            *(float4*)&ra[0] = *(const float4*)&As[kk][ty * 8];
            *(float4*)&ra[4] = *(const float4*)&As[kk][ty * 8 + 4];
            *(float4*)&rb[0] = *(const float4*)&Bs[kk][tx * 8];
            *(float4*)&rb[4] = *(const float4*)&Bs[kk][tx * 8 + 4];
#pragma unroll
            for (int i = 0; i < 8; i++)
#pragma unroll
                for (int j = 0; j < 8; j++)
                    acc[i][j] = fmaf(ra[i], rb[j], acc[i][j]);
        }
        __syncthreads();
    }

#pragma unroll
    for (int i = 0; i < 8; i++) {
        size_t r = (size_t)(brow + ty * 8 + i);
#pragma unroll
        for (int j = 0; j < 8; j += 4) {
            int c = bcol + tx * 8 + j;
            float4 o;
            o.x = acc[i][j + 0] + bias[c + 0];
            o.y = acc[i][j + 1] + bias[c + 1];
            o.z = acc[i][j + 2] + bias[c + 2];
            o.w = acc[i][j + 3] + bias[c + 3];
            *(float4*)(C + r * N + c) = o;
        }
    }
}

// ---------------------------------------------------------------------------
// Flash attention (fp32, online softmax).
// Grid: (S/64, B*H). Block: 128 threads.
// Each block: 64 queries of one (b,h); streams 64-key tiles.
// Thread micro-tiles: scores 4q x 8k, output 4q x 8d.
// smem rows stored with additive rotate to avoid bank conflicts:
//   element (r, c) lives at column (c + 4*((r>>3) + (r&7))) & 63
// ---------------------------------------------------------------------------
__device__ __forceinline__ int rot_of(int r) {
    return (((r >> 3) + (r & 7)) << 2);
}

__global__ __launch_bounds__(128)
void attn_kernel(const float* __restrict__ qkv, float* __restrict__ ctx) {
    __shared__ float Qs[64][64];
    __shared__ float KP[64][64];   // K tile during scoring, then P (probs)
    __shared__ float Vs[64][64];

    int tid = threadIdx.x;
    int qg  = tid >> 3;            // 0..15  -> queries 4*qg .. 4*qg+3
    int kg  = tid & 7;             // 0..7   -> keys/dims 8*kg .. 8*kg+7
    int bh  = blockIdx.y;
    int b   = bh >> 4;
    int h   = bh & 15;
    int q0  = blockIdx.x * 64;

    const float* base = qkv + (size_t)b * S_ * 3 * D_;
    const float scale = 0.125f;    // 1/sqrt(64)

    int rotq[4], rotk[8];
#pragma unroll
    for (int i = 0; i < 4; i++) rotq[i] = rot_of(4 * qg + i);
#pragma unroll
    for (int j = 0; j < 8; j++) rotk[j] = rot_of(8 * kg + j);

    // Load Q tile (pre-scaled)
    for (int i = tid; i < 64 * 16; i += 128) {
        int r  = i >> 4;
        int c4 = (i & 15) << 2;
        float4 v = *(const float4*)(base + (size_t)(q0 + r) * (3 * D_) + h * HD_ + c4);
        int cc = (c4 + rot_of(r)) & 63;
        Qs[r][cc + 0] = v.x * scale;
        Qs[r][cc + 1] = v.y * scale;
        Qs[r][cc + 2] = v.z * scale;
        Qs[r][cc + 3] = v.w * scale;
    }

    float m[4], l[4], acc[4][8];
#pragma unroll
    for (int i = 0; i < 4; i++) { m[i] = -1e30f; l[i] = 0.f; }
#pragma unroll
    for (int i = 0; i < 4; i++)
#pragma unroll
        for (int j = 0; j < 8; j++) acc[i][j] = 0.f;

    for (int kt = 0; kt < S_; kt += 64) {
        __syncthreads();   // prev tile fully consumed (also covers Q load, iter 0)

        // Load K and V tiles (swizzled)
        for (int i = tid; i < 64 * 16; i += 128) {
            int r  = i >> 4;
            int c4 = (i & 15) << 2;
            const float* rp = base + (size_t)(kt + r) * (3 * D_) + h * HD_ + c4;
            int cc = (c4 + rot_of(r)) & 63;
            *(float4*)&KP[r][cc] = *(const float4*)(rp + D_);
            *(float4*)&Vs[r][cc] = *(const float4*)(rp + 2 * D_);
        }
        __syncthreads();

        // Scores: s[4][8] = Q(4q) . K(8k)
        float s[4][8];
#pragma unroll
        for (int i = 0; i < 4; i++)
#pragma unroll
            for (int j = 0; j < 8; j++) s[i][j] = 0.f;

        for (int d = 0; d < 64; d++) {
            float qv[4], kv[8];
#pragma unroll
            for (int i = 0; i < 4; i++)
                qv[i] = Qs[4 * qg + i][(d + rotq[i]) & 63];
#pragma unroll
            for (int j = 0; j < 8; j++)
                kv[j] = KP[8 * kg + j][(d + rotk[j]) & 63];
#pragma unroll
            for (int i = 0; i < 4; i++)
#pragma unroll
                for (int j = 0; j < 8; j++)
                    s[i][j] = fmaf(qv[i], kv[j], s[i][j]);
        }

        // Online softmax (8 lanes share each query row)
#pragma unroll
        for (int i = 0; i < 4; i++) {
            float mt = s[i][0];
#pragma unroll
            for (int j = 1; j < 8; j++) mt = fmaxf(mt, s[i][j]);
            mt = fmaxf(mt, __shfl_xor_sync(0xffffffffu, mt, 1));
            mt = fmaxf(mt, __shfl_xor_sync(0xffffffffu, mt, 2));
            mt = fmaxf(mt, __shfl_xor_sync(0xffffffffu, mt, 4));
            float mn    = fmaxf(m[i], mt);
            float alpha = __expf(m[i] - mn);
            m[i] = mn;
            float rs = 0.f;
#pragma unroll
            for (int j = 0; j < 8; j++) {
                float p = __expf(s[i][j] - mn);
                s[i][j] = p;
                rs += p;
            }
            rs += __shfl_xor_sync(0xffffffffu, rs, 1);
            rs += __shfl_xor_sync(0xffffffffu, rs, 2);
            rs += __shfl_xor_sync(0xffffffffu, rs, 4);
            l[i] = l[i] * alpha + rs;
#pragma unroll
            for (int j = 0; j < 8; j++) acc[i][j] *= alpha;
        }

        __syncthreads();   // everyone done reading K from KP

        // Write P into KP (same swizzle, rows = queries, cols = keys)
#pragma unroll
        for (int i = 0; i < 4; i++) {
            int r = 4 * qg + i;
#pragma unroll
            for (int j = 0; j < 8; j++)
                KP[r][(8 * kg + j + rotq[i]) & 63] = s[i][j];
        }
        __syncthreads();

        // O += P @ V  (thread: 4 queries x 8 dims, dims = 8*kg..)
        for (int k = 0; k < 64; k++) {
            int rv = rot_of(k);
            float pv[4], vv[8];
#pragma unroll
            for (int i = 0; i < 4; i++)
                pv[i] = KP[4 * qg + i][(k + rotq[i]) & 63];
#pragma unroll
            for (int j = 0; j < 8; j++)
                vv[j] = Vs[k][(8 * kg + j + rv) & 63];
#pragma unroll
            for (int i = 0; i < 4; i++)
#pragma unroll
                for (int j = 0; j < 8; j++)
                    acc[i][j] = fmaf(pv[i], vv[j], acc[i][j]);
        }
    }

    // Epilogue: normalize and write ctx[b, q, h*64 + d]
#pragma unroll
    for (int i = 0; i < 4; i++) {
        float inv = 1.f / l[i];
        size_t off = ((size_t)b * S_ + q0 + 4 * qg + i) * D_ + h * HD_ + 8 * kg;
        float4 o0, o1;
        o0.x = acc[i][0] * inv; o0.y = acc[i][1] * inv;
        o0.z = acc[i][2] * inv; o0.w = acc[i][3] * inv;
        o1.x = acc[i][4] * inv; o1.y = acc[i][5] * inv;
        o1.z = acc[i][6] * inv; o1.w = acc[i][7] * inv;
        *(float4*)(ctx + off)     = o0;
        *(float4*)(ctx + off + 4) = o1;
    }
}

// ---------------------------------------------------------------------------
// Launch
// ---------------------------------------------------------------------------
extern "C" void kernel_launch(void* const* d_in, const int* in_sizes, int n_in,
                              void* d_out, int out_size) {
    const float* x    = (const float*)d_in[0];
    const float* Wqkv = (const float*)d_in[1];
    const float* bqkv = (const float*)d_in[2];
    const float* Wout = (const float*)d_in[3];
    const float* bout = (const float*)d_in[4];
    float* out = (float*)d_out;

    void* qkv_p = nullptr;
    void* ctx_p = nullptr;
    cudaGetSymbolAddress(&qkv_p, g_qkv);
    cudaGetSymbolAddress(&ctx_p, g_ctx);
    float* qkv = (float*)qkv_p;
    float* ctx = (float*)ctx_p;

    const int M = B_ * S_;  // 4096

    // 1) QKV projection: [4096,1024] @ [1024,3072] + b
    sgemm_bias<<<dim3(3 * D_ / 128, M / 128), 256>>>(x, Wqkv, bqkv, qkv,
                                                     M, 3 * D_, D_);
    // 2) Attention
    attn_kernel<<<dim3(S_ / 64, B_ * H_), 128>>>(qkv, ctx);

    // 3) Output projection: [4096,1024] @ [1024,1024] + b
    sgemm_bias<<<dim3(D_ / 128, M / 128), 256>>>(ctx, Wout, bout, out,
                                                 M, D_, D_);
}

// round 3
// speedup vs baseline: 1.3877x; 1.3877x over previous
#include <cuda_runtime.h>
#include <stdint.h>
#include <math.h>

#define B_  2
#define S_  2048
#define D_  1024
#define H_  16
#define HD_ 64
#define MTOT (B_ * S_)           // 4096

// ---------------------------------------------------------------------------
// Scratch (__device__ globals: allocation-free rule)
// ---------------------------------------------------------------------------
__device__ float g_qkv[(size_t)B_ * S_ * 3 * D_];   // [B,S,3D]
__device__ float g_ctx[(size_t)B_ * S_ * D_];       // [B,S,D]
__device__ float g_xt[(size_t)MTOT * D_];           // x, tf32-rounded
__device__ float g_wqkv_t[(size_t)3 * D_ * D_];     // W_qkv^T [3D, D]
__device__ float g_wout_t[(size_t)D_ * D_];         // W_out^T [D, D]

// ---------------------------------------------------------------------------
// Helpers (baseline-PTX only: cp.async, ldmatrix, mma.sync — no tcgen05)
// ---------------------------------------------------------------------------
__device__ __forceinline__ uint32_t smem_u32(const void* p) {
    uint32_t a;
    asm("{ .reg .u64 t; cvta.to.shared.u64 t, %1; cvt.u32.u64 %0, t; }"
        : "=r"(a) : "l"(p));
    return a;
}
__device__ __forceinline__ float rnd_tf32(float x) {
    uint32_t u;
    asm("cvt.rna.tf32.f32 %0, %1;" : "=r"(u) : "f"(x));
    return __uint_as_float(u);
}
__device__ __forceinline__ void cp16(uint32_t dst, const void* src) {
    asm volatile("cp.async.cg.shared.global [%0], [%1], 16;"
                 :: "r"(dst), "l"(src));
}
__device__ __forceinline__ void cp_commit() {
    asm volatile("cp.async.commit_group;");
}

// SW128-style swizzle within a [row][32 floats] tile (128B rows):
// swizzled addr = row*128 + (bytecol ^ ((row&7)*16)), bytecol < 128.
__device__ __forceinline__ uint32_t tile_addr(uint32_t base, int row, int bc) {
    return base + (uint32_t)(row * 128) + (uint32_t)(bc ^ ((row & 7) << 4));
}

__device__ __forceinline__ void ldsm_x4(uint32_t addr, uint32_t* r) {
    asm volatile("ldmatrix.sync.aligned.m8n8.x4.shared.b16 {%0,%1,%2,%3}, [%4];"
                 : "=r"(r[0]), "=r"(r[1]), "=r"(r[2]), "=r"(r[3]) : "r"(addr));
}
__device__ __forceinline__ void ldsm_x2(uint32_t addr, uint32_t* r) {
    asm volatile("ldmatrix.sync.aligned.m8n8.x2.shared.b16 {%0,%1}, [%2];"
                 : "=r"(r[0]), "=r"(r[1]) : "r"(addr));
}
__device__ __forceinline__ void mma_tf32(float* c, const uint32_t* a,
                                         const uint32_t* b) {
    asm volatile(
        "mma.sync.aligned.m16n8k8.row.col.f32.tf32.tf32.f32 "
        "{%0,%1,%2,%3}, {%4,%5,%6,%7}, {%8,%9}, {%0,%1,%2,%3};"
        : "+f"(c[0]), "+f"(c[1]), "+f"(c[2]), "+f"(c[3])
        : "r"(a[0]), "r"(a[1]), "r"(a[2]), "r"(a[3]), "r"(b[0]), "r"(b[1]));
}

// ---------------------------------------------------------------------------
// Pre-pass kernels: tf32 rounding (+ transpose for weights)
// ---------------------------------------------------------------------------
__global__ void round_tf32_vec4(const float* __restrict__ in,
                                float* __restrict__ out, int n4) {
    int i = blockIdx.x * blockDim.x + threadIdx.x;
    if (i < n4) {
        float4 v = ((const float4*)in)[i];
        v.x = rnd_tf32(v.x); v.y = rnd_tf32(v.y);
        v.z = rnd_tf32(v.z); v.w = rnd_tf32(v.w);
        ((float4*)out)[i] = v;
    }
}

// W: [K,N] row-major -> Wt: [N,K] row-major, tf32-rounded
__global__ void transpose_round(const float* __restrict__ W,
                                float* __restrict__ Wt, int K, int N) {
    __shared__ float t[32][33];
    int bx = blockIdx.x * 32;
    int by = blockIdx.y * 32;
    int x = threadIdx.x, y = threadIdx.y;   // block (32, 8)
#pragma unroll
    for (int j = 0; j < 32; j += 8)
        t[y + j][x] = W[(size_t)(by + y + j) * N + bx + x];
    __syncthreads();
#pragma unroll
    for (int j = 0; j < 32; j += 8)
        Wt[(size_t)(bx + y + j) * K + by + x] = rnd_tf32(t[x][y + j]);
}

// ---------------------------------------------------------------------------
// Tensor-core tf32 GEMM + bias (mma.sync path, sm_80-compatible PTX).
// C[M,N] = A[M,K] @ Bt[N,K]^T + bias.  K = 1024.
// Block: 256 thr (8 warps, 2x4), tile 128x128, BK=32, cp.async double buffer.
// Warp tile 64x32 -> 4 m-tiles(16) x 4 n-tiles(8), mma.m16n8k8.
// ---------------------------------------------------------------------------
#define GK    1024
#define BK    32
#define NKIT  (GK / BK)         // 32
#define STAGE_BYTES 32768       // A tile 16KB + B tile 16KB
#define GSMEM_BYTES (2 * STAGE_BYTES)

__global__ __launch_bounds__(256, 2)
void gemm_tc(const float* __restrict__ A, const float* __restrict__ Bt,
             const float* __restrict__ bias, float* __restrict__ C, int N) {
    extern __shared__ char smem[];
    uint32_t sbase = smem_u32(smem);

    int tid  = threadIdx.x;
    int wid  = tid >> 5;
    int lane = tid & 31;
    int wm   = wid >> 2;            // 0..1  (M)
    int wn   = wid & 3;             // 0..3  (N)
    int brow = blockIdx.y * 128;
    int bcol = blockIdx.x * 128;

    uint32_t aB[2], bB[2];
    aB[0] = sbase;                 bB[0] = sbase + 16384;
    aB[1] = sbase + STAGE_BYTES;   bB[1] = aB[1] + 16384;

    const float* Agp = A  + (size_t)brow * GK;
    const float* Bgp = Bt + (size_t)bcol * GK;

    // cp.async mapping: chunk c (0..1023): row=c>>3, 16B-unit col=c&7
    int cr = tid >> 3, cc16 = (tid & 7) * 16;

    // ldmatrix lane roles
    int a_row_l = ((lane >> 3) & 1) * 8 + (lane & 7);   // row within 16
    int a_bc_l  = (lane >> 4) * 16;                     // k-half byte offset
    int b_row_l = lane & 7;                             // row within 8
    int b_bc_l  = ((lane >> 3) & 1) * 16;

    float acc[4][4][4];
#pragma unroll
    for (int i = 0; i < 4; i++)
#pragma unroll
        for (int j = 0; j < 4; j++)
#pragma unroll
            for (int k = 0; k < 4; k++) acc[i][j][k] = 0.f;

    // ---- prologue: stage 0
#pragma unroll
    for (int j = 0; j < 4; j++) {
        int row = cr + j * 32;
        uint32_t off = tile_addr(0, row, cc16);
        cp16(aB[0] + off, Agp + (size_t)row * GK + (cc16 >> 2));
        cp16(bB[0] + off, Bgp + (size_t)row * GK + (cc16 >> 2));
    }
    cp_commit();

    for (int it = 0; it < NKIT; it++) {
        int buf = it & 1;
        if (it + 1 < NKIT) {
            int nxt = buf ^ 1;
            int k0  = (it + 1) * BK;
#pragma unroll
            for (int j = 0; j < 4; j++) {
                int row = cr + j * 32;
                uint32_t off = tile_addr(0, row, cc16);
                cp16(aB[nxt] + off, Agp + (size_t)row * GK + k0 + (cc16 >> 2));
                cp16(bB[nxt] + off, Bgp + (size_t)row * GK + k0 + (cc16 >> 2));
            }
            cp_commit();
            asm volatile("cp.async.wait_group 1;");
        } else {
            asm volatile("cp.async.wait_group 0;");
        }
        __syncthreads();

        uint32_t aS = aB[buf], bS = bB[buf];
#pragma unroll
        for (int s = 0; s < 4; s++) {
            uint32_t af[4][4], bf[4][2];
#pragma unroll
            for (int mt = 0; mt < 4; mt++)
                ldsm_x4(tile_addr(aS, wm * 64 + mt * 16 + a_row_l,
                                  s * 32 + a_bc_l), af[mt]);
#pragma unroll
            for (int nt = 0; nt < 4; nt++)
                ldsm_x2(tile_addr(bS, wn * 32 + nt * 8 + b_row_l,
                                  s * 32 + b_bc_l), bf[nt]);
#pragma unroll
            for (int mt = 0; mt < 4; mt++)
#pragma unroll
                for (int nt = 0; nt < 4; nt++)
                    mma_tf32(acc[mt][nt], af[mt], bf[nt]);
        }
        __syncthreads();
    }

    // ---- epilogue: c0:(r, c) c1:(r, c+1) c2:(r+8, c) c3:(r+8, c+1)
#pragma unroll
    for (int mt = 0; mt < 4; mt++) {
        int r0 = brow + wm * 64 + mt * 16 + (lane >> 2);
#pragma unroll
        for (int nt = 0; nt < 4; nt++) {
            int c = bcol + wn * 32 + nt * 8 + 2 * (lane & 3);
            float b0 = bias[c], b1 = bias[c + 1];
            float2 o0 = make_float2(acc[mt][nt][0] + b0, acc[mt][nt][1] + b1);
            float2 o1 = make_float2(acc[mt][nt][2] + b0, acc[mt][nt][3] + b1);
            *(float2*)(C + (size_t)r0 * N + c)       = o0;
            *(float2*)(C + (size_t)(r0 + 8) * N + c) = o1;
        }
    }
}

// ---------------------------------------------------------------------------
// Flash attention (fp32, online softmax) — unchanged.
// ---------------------------------------------------------------------------
__device__ __forceinline__ int rot_of(int r) {
    return (((r >> 3) + (r & 7)) << 2);
}

__global__ __launch_bounds__(128)
void attn_kernel(const float* __restrict__ qkv, float* __restrict__ ctx) {
    __shared__ float Qs[64][64];
    __shared__ float KP[64][64];
    __shared__ float Vs[64][64];

    int tid = threadIdx.x;
    int qg  = tid >> 3;
    int kg  = tid & 7;
    int bh  = blockIdx.y;
    int b   = bh >> 4;
    int h   = bh & 15;
    int q0  = blockIdx.x * 64;

    const float* base = qkv + (size_t)b * S_ * 3 * D_;
    const float scale = 0.125f;

    int rotq[4], rotk[8];
#pragma unroll
    for (int i = 0; i < 4; i++) rotq[i] = rot_of(4 * qg + i);
#pragma unroll
    for (int j = 0; j < 8; j++) rotk[j] = rot_of(8 * kg + j);

    for (int i = tid; i < 64 * 16; i += 128) {
        int r  = i >> 4;
        int c4 = (i & 15) << 2;
        float4 v = *(const float4*)(base + (size_t)(q0 + r) * (3 * D_) + h * HD_ + c4);
        int cc = (c4 + rot_of(r)) & 63;
        Qs[r][cc + 0] = v.x * scale;
        Qs[r][cc + 1] = v.y * scale;
        Qs[r][cc + 2] = v.z * scale;
        Qs[r][cc + 3] = v.w * scale;
    }

    float m[4], l[4], acc[4][8];
#pragma unroll
    for (int i = 0; i < 4; i++) { m[i] = -1e30f; l[i] = 0.f; }
#pragma unroll
    for (int i = 0; i < 4; i++)
#pragma unroll
        for (int j = 0; j < 8; j++) acc[i][j] = 0.f;

    for (int kt = 0; kt < S_; kt += 64) {
        __syncthreads();
        for (int i = tid; i < 64 * 16; i += 128) {
            int r  = i >> 4;
            int c4 = (i & 15) << 2;
            const float* rp = base + (size_t)(kt + r) * (3 * D_) + h * HD_ + c4;
            int cc = (c4 + rot_of(r)) & 63;
            *(float4*)&KP[r][cc] = *(const float4*)(rp + D_);
            *(float4*)&Vs[r][cc] = *(const float4*)(rp + 2 * D_);
        }
        __syncthreads();

        float s[4][8];
#pragma unroll
        for (int i = 0; i < 4; i++)
#pragma unroll
            for (int j = 0; j < 8; j++) s[i][j] = 0.f;

        for (int d = 0; d < 64; d++) {
            float qv[4], kv[8];
#pragma unroll
            for (int i = 0; i < 4; i++)
                qv[i] = Qs[4 * qg + i][(d + rotq[i]) & 63];
#pragma unroll
            for (int j = 0; j < 8; j++)
                kv[j] = KP[8 * kg + j][(d + rotk[j]) & 63];
#pragma unroll
            for (int i = 0; i < 4; i++)
#pragma unroll
                for (int j = 0; j < 8; j++)
                    s[i][j] = fmaf(qv[i], kv[j], s[i][j]);
        }

#pragma unroll
        for (int i = 0; i < 4; i++) {
            float mt = s[i][0];
#pragma unroll
            for (int j = 1; j < 8; j++) mt = fmaxf(mt, s[i][j]);
            mt = fmaxf(mt, __shfl_xor_sync(0xffffffffu, mt, 1));
            mt = fmaxf(mt, __shfl_xor_sync(0xffffffffu, mt, 2));
            mt = fmaxf(mt, __shfl_xor_sync(0xffffffffu, mt, 4));
            float mn    = fmaxf(m[i], mt);
            float alpha = __expf(m[i] - mn);
            m[i] = mn;
            float rs = 0.f;
#pragma unroll
            for (int j = 0; j < 8; j++) {
                float p = __expf(s[i][j] - mn);
                s[i][j] = p;
                rs += p;
            }
            rs += __shfl_xor_sync(0xffffffffu, rs, 1);
            rs += __shfl_xor_sync(0xffffffffu, rs, 2);
            rs += __shfl_xor_sync(0xffffffffu, rs, 4);
            l[i] = l[i] * alpha + rs;
#pragma unroll
            for (int j = 0; j < 8; j++) acc[i][j] *= alpha;
        }

        __syncthreads();

#pragma unroll
        for (int i = 0; i < 4; i++) {
            int r = 4 * qg + i;
#pragma unroll
            for (int j = 0; j < 8; j++)
                KP[r][(8 * kg + j + rotq[i]) & 63] = s[i][j];
        }
        __syncthreads();

        for (int k = 0; k < 64; k++) {
            int rv = rot_of(k);
            float pv[4], vv[8];
#pragma unroll
            for (int i = 0; i < 4; i++)
                pv[i] = KP[4 * qg + i][(k + rotq[i]) & 63];
#pragma unroll
            for (int j = 0; j < 8; j++)
                vv[j] = Vs[k][(8 * kg + j + rv) & 63];
#pragma unroll
            for (int i = 0; i < 4; i++)
#pragma unroll
                for (int j = 0; j < 8; j++)
                    acc[i][j] = fmaf(pv[i], vv[j], acc[i][j]);
        }
    }

#pragma unroll
    for (int i = 0; i < 4; i++) {
        float inv = 1.f / l[i];
        size_t off = ((size_t)b * S_ + q0 + 4 * qg + i) * D_ + h * HD_ + 8 * kg;
        float4 o0, o1;
        o0.x = rnd_tf32(acc[i][0] * inv); o0.y = rnd_tf32(acc[i][1] * inv);
        o0.z = rnd_tf32(acc[i][2] * inv); o0.w = rnd_tf32(acc[i][3] * inv);
        o1.x = rnd_tf32(acc[i][4] * inv); o1.y = rnd_tf32(acc[i][5] * inv);
        o1.z = rnd_tf32(acc[i][6] * inv); o1.w = rnd_tf32(acc[i][7] * inv);
        *(float4*)(ctx + off)     = o0;
        *(float4*)(ctx + off + 4) = o1;
    }
}

// ---------------------------------------------------------------------------
// Launch
// ---------------------------------------------------------------------------
extern "C" void kernel_launch(void* const* d_in, const int* in_sizes, int n_in,
                              void* d_out, int out_size) {
    const float* x    = (const float*)d_in[0];
    const float* Wqkv = (const float*)d_in[1];
    const float* bqkv = (const float*)d_in[2];
    const float* Wout = (const float*)d_in[3];
    const float* bout = (const float*)d_in[4];
    float* out = (float*)d_out;

    void *qkv_p, *ctx_p, *xt_p, *wq_p, *wo_p;
    cudaGetSymbolAddress(&qkv_p, g_qkv);
    cudaGetSymbolAddress(&ctx_p, g_ctx);
    cudaGetSymbolAddress(&xt_p,  g_xt);
    cudaGetSymbolAddress(&wq_p,  g_wqkv_t);
    cudaGetSymbolAddress(&wo_p,  g_wout_t);
    float* qkv   = (float*)qkv_p;
    float* ctx   = (float*)ctx_p;
    float* xt    = (float*)xt_p;
    float* wqkvt = (float*)wq_p;
    float* woutt = (float*)wo_p;

    cudaFuncSetAttribute(gemm_tc, cudaFuncAttributeMaxDynamicSharedMemorySize,
                         GSMEM_BYTES);

    // Pre-pass: tf32-round x; transpose+round weights to [N,K]
    int n4 = MTOT * D_ / 4;
    round_tf32_vec4<<<(n4 + 255) / 256, 256>>>(x, xt, n4);
    transpose_round<<<dim3(3 * D_ / 32, D_ / 32), dim3(32, 8)>>>(Wqkv, wqkvt, D_, 3 * D_);
    transpose_round<<<dim3(D_ / 32, D_ / 32), dim3(32, 8)>>>(Wout, woutt, D_, D_);

    // 1) QKV projection (mma.sync tf32): [4096,1024] @ [1024,3072] + b
    gemm_tc<<<dim3(3 * D_ / 128, MTOT / 128), 256, GSMEM_BYTES>>>(xt, wqkvt, bqkv, qkv, 3 * D_);

    // 2) Attention (fp32 flash)
    attn_kernel<<<dim3(S_ / 64, B_ * H_), 128>>>(qkv, ctx);

    // 3) Output projection (mma.sync tf32): [4096,1024] @ [1024,1024] + b
    gemm_tc<<<dim3(D_ / 128, MTOT / 128), 256, GSMEM_BYTES>>>(ctx, woutt, bout, out, D_);
}

// round 4
// speedup vs baseline: 4.5497x; 3.2785x over previous
#include <cuda_runtime.h>
#include <stdint.h>
#include <math.h>

#define B_  2
#define S_  2048
#define D_  1024
#define H_  16
#define HD_ 64
#define MTOT (B_ * S_)           // 4096

// ---------------------------------------------------------------------------
// Scratch (__device__ globals: allocation-free rule)
// ---------------------------------------------------------------------------
__device__ float g_qkv[(size_t)B_ * S_ * 3 * D_];   // [B,S,3D] (tf32-rounded)
__device__ float g_ctx[(size_t)B_ * S_ * D_];       // [B,S,D]  (tf32-rounded)
__device__ float g_xt[(size_t)MTOT * D_];           // x, tf32-rounded
__device__ float g_wqkv_t[(size_t)3 * D_ * D_];     // W_qkv^T [3D, D]
__device__ float g_wout_t[(size_t)D_ * D_];         // W_out^T [D, D]

// ---------------------------------------------------------------------------
// Helpers (baseline-PTX only: cp.async, ldmatrix, mma.sync)
// ---------------------------------------------------------------------------
__device__ __forceinline__ uint32_t smem_u32(const void* p) {
    uint32_t a;
    asm("{ .reg .u64 t; cvta.to.shared.u64 t, %1; cvt.u32.u64 %0, t; }"
        : "=r"(a) : "l"(p));
    return a;
}
__device__ __forceinline__ float rnd_tf32(float x) {
    uint32_t u;
    asm("cvt.rna.tf32.f32 %0, %1;" : "=r"(u) : "f"(x));
    return __uint_as_float(u);
}
__device__ __forceinline__ void cp16(uint32_t dst, const void* src) {
    asm volatile("cp.async.cg.shared.global [%0], [%1], 16;"
                 :: "r"(dst), "l"(src));
}
__device__ __forceinline__ void cp_commit() {
    asm volatile("cp.async.commit_group;");
}
__device__ __forceinline__ void ldsm_x4(uint32_t addr, uint32_t* r) {
    asm volatile("ldmatrix.sync.aligned.m8n8.x4.shared.b16 {%0,%1,%2,%3}, [%4];"
                 : "=r"(r[0]), "=r"(r[1]), "=r"(r[2]), "=r"(r[3]) : "r"(addr));
}
__device__ __forceinline__ void ldsm_x2(uint32_t addr, uint32_t* r) {
    asm volatile("ldmatrix.sync.aligned.m8n8.x2.shared.b16 {%0,%1}, [%2];"
                 : "=r"(r[0]), "=r"(r[1]) : "r"(addr));
}
__device__ __forceinline__ void mma_tf32(float* c, const uint32_t* a,
                                         const uint32_t* b) {
    asm volatile(
        "mma.sync.aligned.m16n8k8.row.col.f32.tf32.tf32.f32 "
        "{%0,%1,%2,%3}, {%4,%5,%6,%7}, {%8,%9}, {%0,%1,%2,%3};"
        : "+f"(c[0]), "+f"(c[1]), "+f"(c[2]), "+f"(c[3])
        : "r"(a[0]), "r"(a[1]), "r"(a[2]), "r"(a[3]), "r"(b[0]), "r"(b[1]));
}

// GEMM tile addressing: 128B rows (32 floats)
__device__ __forceinline__ uint32_t tile_addr(uint32_t base, int row, int bc) {
    return base + (uint32_t)(row * 128) + (uint32_t)(bc ^ ((row & 7) << 4));
}
// Attention tile addressing: 256B rows (64 floats), 2-level XOR swizzle
__device__ __forceinline__ uint32_t swzA(int row, int bc) {
    int nib = ((row & 7) ^ ((row >> 3) & 7)) << 4;
    return (uint32_t)(row * 256 + (bc ^ nib));
}

// ---------------------------------------------------------------------------
// Pre-pass kernels
// ---------------------------------------------------------------------------
__global__ void round_tf32_vec4(const float* __restrict__ in,
                                float* __restrict__ out, int n4) {
    int i = blockIdx.x * blockDim.x + threadIdx.x;
    if (i < n4) {
        float4 v = ((const float4*)in)[i];
        v.x = rnd_tf32(v.x); v.y = rnd_tf32(v.y);
        v.z = rnd_tf32(v.z); v.w = rnd_tf32(v.w);
        ((float4*)out)[i] = v;
    }
}

__global__ void transpose_round(const float* __restrict__ W,
                                float* __restrict__ Wt, int K, int N) {
    __shared__ float t[32][33];
    int bx = blockIdx.x * 32;
    int by = blockIdx.y * 32;
    int x = threadIdx.x, y = threadIdx.y;   // block (32, 8)
#pragma unroll
    for (int j = 0; j < 32; j += 8)
        t[y + j][x] = W[(size_t)(by + y + j) * N + bx + x];
    __syncthreads();
#pragma unroll
    for (int j = 0; j < 32; j += 8)
        Wt[(size_t)(bx + y + j) * K + by + x] = rnd_tf32(t[x][y + j]);
}

// ---------------------------------------------------------------------------
// Tensor-core tf32 GEMM + bias (mma.sync), as validated in R3.
// do_round: tf32-round outputs (when result feeds another tf32 GEMM/attn).
// ---------------------------------------------------------------------------
#define GK    1024
#define BK    32
#define NKIT  (GK / BK)
#define STAGE_BYTES 32768
#define GSMEM_BYTES (2 * STAGE_BYTES)

__global__ __launch_bounds__(256, 2)
void gemm_tc(const float* __restrict__ A, const float* __restrict__ Bt,
             const float* __restrict__ bias, float* __restrict__ C, int N,
             int do_round) {
    extern __shared__ char smem[];
    uint32_t sbase = smem_u32(smem);

    int tid  = threadIdx.x;
    int wid  = tid >> 5;
    int lane = tid & 31;
    int wm   = wid >> 2;
    int wn   = wid & 3;
    int brow = blockIdx.y * 128;
    int bcol = blockIdx.x * 128;

    uint32_t aB[2], bB[2];
    aB[0] = sbase;                 bB[0] = sbase + 16384;
    aB[1] = sbase + STAGE_BYTES;   bB[1] = aB[1] + 16384;

    const float* Agp = A  + (size_t)brow * GK;
    const float* Bgp = Bt + (size_t)bcol * GK;

    int cr = tid >> 3, cc16 = (tid & 7) * 16;

    int a_row_l = ((lane >> 3) & 1) * 8 + (lane & 7);
    int a_bc_l  = (lane >> 4) * 16;
    int b_row_l = lane & 7;
    int b_bc_l  = ((lane >> 3) & 1) * 16;

    float acc[4][4][4];
#pragma unroll
    for (int i = 0; i < 4; i++)
#pragma unroll
        for (int j = 0; j < 4; j++)
#pragma unroll
            for (int k = 0; k < 4; k++) acc[i][j][k] = 0.f;

#pragma unroll
    for (int j = 0; j < 4; j++) {
        int row = cr + j * 32;
        uint32_t off = tile_addr(0, row, cc16);
        cp16(aB[0] + off, Agp + (size_t)row * GK + (cc16 >> 2));
        cp16(bB[0] + off, Bgp + (size_t)row * GK + (cc16 >> 2));
    }
    cp_commit();

    for (int it = 0; it < NKIT; it++) {
        int buf = it & 1;
        if (it + 1 < NKIT) {
            int nxt = buf ^ 1;
            int k0  = (it + 1) * BK;
#pragma unroll
            for (int j = 0; j < 4; j++) {
                int row = cr + j * 32;
                uint32_t off = tile_addr(0, row, cc16);
                cp16(aB[nxt] + off, Agp + (size_t)row * GK + k0 + (cc16 >> 2));
                cp16(bB[nxt] + off, Bgp + (size_t)row * GK + k0 + (cc16 >> 2));
            }
            cp_commit();
            asm volatile("cp.async.wait_group 1;");
        } else {
            asm volatile("cp.async.wait_group 0;");
        }
        __syncthreads();

        uint32_t aS = aB[buf], bS = bB[buf];
#pragma unroll
        for (int s = 0; s < 4; s++) {
            uint32_t af[4][4], bf[4][2];
#pragma unroll
            for (int mt = 0; mt < 4; mt++)
                ldsm_x4(tile_addr(aS, wm * 64 + mt * 16 + a_row_l,
                                  s * 32 + a_bc_l), af[mt]);
#pragma unroll
            for (int nt = 0; nt < 4; nt++)
                ldsm_x2(tile_addr(bS, wn * 32 + nt * 8 + b_row_l,
                                  s * 32 + b_bc_l), bf[nt]);
#pragma unroll
            for (int mt = 0; mt < 4; mt++)
#pragma unroll
                for (int nt = 0; nt < 4; nt++)
                    mma_tf32(acc[mt][nt], af[mt], bf[nt]);
        }
        __syncthreads();
    }

#pragma unroll
    for (int mt = 0; mt < 4; mt++) {
        int r0 = brow + wm * 64 + mt * 16 + (lane >> 2);
#pragma unroll
        for (int nt = 0; nt < 4; nt++) {
            int c = bcol + wn * 32 + nt * 8 + 2 * (lane & 3);
            float b0 = bias[c], b1 = bias[c + 1];
            float v00 = acc[mt][nt][0] + b0, v01 = acc[mt][nt][1] + b1;
            float v10 = acc[mt][nt][2] + b0, v11 = acc[mt][nt][3] + b1;
            if (do_round) {
                v00 = rnd_tf32(v00); v01 = rnd_tf32(v01);
                v10 = rnd_tf32(v10); v11 = rnd_tf32(v11);
            }
            *(float2*)(C + (size_t)r0 * N + c)       = make_float2(v00, v01);
            *(float2*)(C + (size_t)(r0 + 8) * N + c) = make_float2(v10, v11);
        }
    }
}

// ---------------------------------------------------------------------------
// Tensor-core flash attention (tf32 mma.sync, online softmax).
// Grid (S/128, B*H), 256 threads (8 warps). Warp w owns q-rows w*16..w*16+15.
// Per 64-key tile: QK^T mma -> register softmax -> P to smem -> PV mma.
// smem: Ps/Qs 32KB | Kt[2] 16KB ea | Vt[2] 16KB ea  = 96KB.
// ---------------------------------------------------------------------------
#define ASMEM_BYTES (32768 + 2 * 16384 + 2 * 16384)

__global__ __launch_bounds__(256, 1)
void attn_tc(const float* __restrict__ qkv, float* __restrict__ ctx) {
    extern __shared__ char smem[];
    uint32_t sbase = smem_u32(smem);
    uint32_t PS    = sbase;
    uint32_t KT[2] = { sbase + 32768, sbase + 32768 + 16384 };
    uint32_t VT[2] = { sbase + 65536, sbase + 65536 + 16384 };

    int tid  = threadIdx.x;
    int wid  = tid >> 5;
    int lane = tid & 31;
    int b    = blockIdx.y >> 4;
    int h    = blockIdx.y & 15;
    int q0   = blockIdx.x * 128;

    const float* base = qkv + (size_t)b * S_ * 3 * D_ + h * HD_;
    const float scale = 0.125f;   // 1/sqrt(64), exact power of 2

    int a_row_l = ((lane >> 3) & 1) * 8 + (lane & 7);
    int a_bc_l  = (lane >> 4) * 16;
    int b_row_l = lane & 7;
    int b_bc_l  = ((lane >> 3) & 1) * 16;

    // ---- Q -> smem (scaled), then cache fragments in registers
    {
        for (int j = 0; j < 8; j++) {
            int idx = tid + j * 256;            // 2048 float4s
            int r   = idx >> 4;
            int c16 = (idx & 15) * 16;          // byte col
            float4 v = *(const float4*)(base + (size_t)(q0 + r) * (3 * D_) + (c16 >> 2));
            v.x *= scale; v.y *= scale; v.z *= scale; v.w *= scale;
            uint32_t ad = PS + swzA(r, c16);
            asm volatile("st.shared.v4.f32 [%0], {%1,%2,%3,%4};"
                         :: "r"(ad), "f"(v.x), "f"(v.y), "f"(v.z), "f"(v.w));
        }
    }
    __syncthreads();

    uint32_t qf[8][4];
#pragma unroll
    for (int ks = 0; ks < 8; ks++)
        ldsm_x4(PS + swzA(wid * 16 + a_row_l, ks * 32 + a_bc_l), qf[ks]);
    __syncthreads();   // Qs fully consumed -> becomes Ps

    // ---- K/V fill helpers (tile kt into buf)
    // K: cp.async, 64 rows x 16 chunks; V: LDG float4 + transposed scalar STS.
    float m0 = -1e30f, m1 = -1e30f, l0 = 0.f, l1 = 0.f;
    float o[8][4];
#pragma unroll
    for (int nt = 0; nt < 8; nt++)
#pragma unroll
        for (int k = 0; k < 4; k++) o[nt][k] = 0.f;

    // prologue fill: tile 0 -> buf 0
    {
        const float* kbase = base + D_;
        const float* vbase = base + 2 * D_;
#pragma unroll
        for (int j = 0; j < 4; j++) {
            int idx  = tid + j * 256;           // 1024 chunks
            int krow = idx >> 4;
            int c16  = (idx & 15) * 16;
            cp16(KT[0] + swzA(krow, c16),
                 kbase + (size_t)krow * (3 * D_) + (c16 >> 2));
        }
        cp_commit();
#pragma unroll
        for (int j = 0; j < 4; j++) {
            int idx = tid + j * 256;
            int key = idx >> 4;
            int d4  = (idx & 15) * 4;
            float4 v = *(const float4*)(vbase + (size_t)key * (3 * D_) + d4);
            float vv[4] = {v.x, v.y, v.z, v.w};
#pragma unroll
            for (int e = 0; e < 4; e++) {
                uint32_t ad = VT[0] + swzA(d4 + e, key * 4);
                asm volatile("st.shared.f32 [%0], %1;" :: "r"(ad), "f"(vv[e]));
            }
        }
    }

    const int NT = S_ / 64;   // 32 key tiles
    for (int kt = 0; kt < NT; kt++) {
        int buf = kt & 1;
        asm volatile("cp.async.wait_group 0;");
        __syncthreads();   // buf ready; prior buf^1 consumers done

        if (kt + 1 < NT) {
            int nxt = buf ^ 1;
            const float* kbase = base + (size_t)(kt + 1) * 64 * (3 * D_) + D_;
            const float* vbase = kbase + D_;
#pragma unroll
            for (int j = 0; j < 4; j++) {
                int idx  = tid + j * 256;
                int krow = idx >> 4;
                int c16  = (idx & 15) * 16;
                cp16(KT[nxt] + swzA(krow, c16),
                     kbase + (size_t)krow * (3 * D_) + (c16 >> 2));
            }
            cp_commit();
#pragma unroll
            for (int j = 0; j < 4; j++) {
                int idx = tid + j * 256;
                int key = idx >> 4;
                int d4  = (idx & 15) * 4;
                float4 v = *(const float4*)(vbase + (size_t)key * (3 * D_) + d4);
                float vv[4] = {v.x, v.y, v.z, v.w};
#pragma unroll
                for (int e = 0; e < 4; e++) {
                    uint32_t ad = VT[nxt] + swzA(d4 + e, key * 4);
                    asm volatile("st.shared.f32 [%0], %1;" :: "r"(ad), "f"(vv[e]));
                }
            }
        }

        // ---- QK^T: sc[nt][..] over 64 keys
        float sc[8][4];
#pragma unroll
        for (int nt = 0; nt < 8; nt++)
#pragma unroll
            for (int k = 0; k < 4; k++) sc[nt][k] = 0.f;

#pragma unroll
        for (int ks = 0; ks < 8; ks++) {
            uint32_t bf[8][2];
#pragma unroll
            for (int nt = 0; nt < 8; nt++)
                ldsm_x2(KT[buf] + swzA(nt * 8 + b_row_l, ks * 32 + b_bc_l), bf[nt]);
#pragma unroll
            for (int nt = 0; nt < 8; nt++)
                mma_tf32(sc[nt], qf[ks], bf[nt]);
        }

        // ---- online softmax (rows r = lane>>2 and r+8 within warp tile)
        {
            float mt = -1e30f;
#pragma unroll
            for (int nt = 0; nt < 8; nt++)
                mt = fmaxf(mt, fmaxf(sc[nt][0], sc[nt][1]));
            mt = fmaxf(mt, __shfl_xor_sync(0xffffffffu, mt, 1));
            mt = fmaxf(mt, __shfl_xor_sync(0xffffffffu, mt, 2));
            float mn = fmaxf(m0, mt);
            float al = __expf(m0 - mn);
            m0 = mn;
            float rs = 0.f;
#pragma unroll
            for (int nt = 0; nt < 8; nt++) {
                sc[nt][0] = __expf(sc[nt][0] - mn);
                sc[nt][1] = __expf(sc[nt][1] - mn);
                rs += sc[nt][0] + sc[nt][1];
            }
            rs += __shfl_xor_sync(0xffffffffu, rs, 1);
            rs += __shfl_xor_sync(0xffffffffu, rs, 2);
            l0 = l0 * al + rs;
#pragma unroll
            for (int nt = 0; nt < 8; nt++) { o[nt][0] *= al; o[nt][1] *= al; }
        }
        {
            float mt = -1e30f;
#pragma unroll
            for (int nt = 0; nt < 8; nt++)
                mt = fmaxf(mt, fmaxf(sc[nt][2], sc[nt][3]));
            mt = fmaxf(mt, __shfl_xor_sync(0xffffffffu, mt, 1));
            mt = fmaxf(mt, __shfl_xor_sync(0xffffffffu, mt, 2));
            float mn = fmaxf(m1, mt);
            float al = __expf(m1 - mn);
            m1 = mn;
            float rs = 0.f;
#pragma unroll
            for (int nt = 0; nt < 8; nt++) {
                sc[nt][2] = __expf(sc[nt][2] - mn);
                sc[nt][3] = __expf(sc[nt][3] - mn);
                rs += sc[nt][2] + sc[nt][3];
            }
            rs += __shfl_xor_sync(0xffffffffu, rs, 1);
            rs += __shfl_xor_sync(0xffffffffu, rs, 2);
            l1 = l1 * al + rs;
#pragma unroll
            for (int nt = 0; nt < 8; nt++) { o[nt][2] *= al; o[nt][3] *= al; }
        }

        // ---- P (tf32-rounded) -> Ps (own warp's rows only)
        {
            int R0 = wid * 16 + (lane >> 2);
            int bcl = (lane & 3) * 8;
#pragma unroll
            for (int nt = 0; nt < 8; nt++) {
                uint32_t a0 = PS + swzA(R0,     nt * 32 + bcl);
                uint32_t a1 = PS + swzA(R0 + 8, nt * 32 + bcl);
                asm volatile("st.shared.v2.f32 [%0], {%1,%2};"
                             :: "r"(a0), "f"(rnd_tf32(sc[nt][0])), "f"(rnd_tf32(sc[nt][1])));
                asm volatile("st.shared.v2.f32 [%0], {%1,%2};"
                             :: "r"(a1), "f"(rnd_tf32(sc[nt][2])), "f"(rnd_tf32(sc[nt][3])));
            }
        }
        __syncwarp();

        // ---- O += P @ V
#pragma unroll
        for (int ks = 0; ks < 8; ks++) {
            uint32_t af[4];
            ldsm_x4(PS + swzA(wid * 16 + a_row_l, ks * 32 + a_bc_l), af);
            uint32_t bf[8][2];
#pragma unroll
            for (int nt = 0; nt < 8; nt++)
                ldsm_x2(VT[buf] + swzA(nt * 8 + b_row_l, ks * 32 + b_bc_l), bf[nt]);
#pragma unroll
            for (int nt = 0; nt < 8; nt++)
                mma_tf32(o[nt], af, bf[nt]);
        }
        __syncwarp();
    }

    // ---- epilogue: normalize, tf32-round, write ctx[b, q, h*64+d]
    {
        float i0 = 1.f / l0, i1 = 1.f / l1;
        int   r0 = q0 + wid * 16 + (lane >> 2);
        int   cc = h * HD_ + (lane & 3) * 2;
        float* c0 = ctx + ((size_t)b * S_ + r0) * D_ + cc;
        float* c1 = c0 + 8 * D_;
#pragma unroll
        for (int nt = 0; nt < 8; nt++) {
            *(float2*)(c0 + nt * 8) =
                make_float2(rnd_tf32(o[nt][0] * i0), rnd_tf32(o[nt][1] * i0));
            *(float2*)(c1 + nt * 8) =
                make_float2(rnd_tf32(o[nt][2] * i1), rnd_tf32(o[nt][3] * i1));
        }
    }
}

// ---------------------------------------------------------------------------
// Launch
// ---------------------------------------------------------------------------
extern "C" void kernel_launch(void* const* d_in, const int* in_sizes, int n_in,
                              void* d_out, int out_size) {
    const float* x    = (const float*)d_in[0];
    const float* Wqkv = (const float*)d_in[1];
    const float* bqkv = (const float*)d_in[2];
    const float* Wout = (const float*)d_in[3];
    const float* bout = (const float*)d_in[4];
    float* out = (float*)d_out;

    void *qkv_p, *ctx_p, *xt_p, *wq_p, *wo_p;
    cudaGetSymbolAddress(&qkv_p, g_qkv);
    cudaGetSymbolAddress(&ctx_p, g_ctx);
    cudaGetSymbolAddress(&xt_p,  g_xt);
    cudaGetSymbolAddress(&wq_p,  g_wqkv_t);
    cudaGetSymbolAddress(&wo_p,  g_wout_t);
    float* qkv   = (float*)qkv_p;
    float* ctx   = (float*)ctx_p;
    float* xt    = (float*)xt_p;
    float* wqkvt = (float*)wq_p;
    float* woutt = (float*)wo_p;

    cudaFuncSetAttribute(gemm_tc, cudaFuncAttributeMaxDynamicSharedMemorySize,
                         GSMEM_BYTES);
    cudaFuncSetAttribute(attn_tc, cudaFuncAttributeMaxDynamicSharedMemorySize,
                         ASMEM_BYTES);

    // Pre-pass
    int n4 = MTOT * D_ / 4;
    round_tf32_vec4<<<(n4 + 255) / 256, 256>>>(x, xt, n4);
    transpose_round<<<dim3(3 * D_ / 32, D_ / 32), dim3(32, 8)>>>(Wqkv, wqkvt, D_, 3 * D_);
    transpose_round<<<dim3(D_ / 32, D_ / 32), dim3(32, 8)>>>(Wout, woutt, D_, D_);

    // 1) QKV projection (round outputs -> attention consumes tf32)
    gemm_tc<<<dim3(3 * D_ / 128, MTOT / 128), 256, GSMEM_BYTES>>>(
        xt, wqkvt, bqkv, qkv, 3 * D_, 1);

    // 2) Attention (tensor-core flash)
    attn_tc<<<dim3(S_ / 128, B_ * H_), 256, ASMEM_BYTES>>>(qkv, ctx);

    // 3) Output projection (no rounding — final output)
    gemm_tc<<<dim3(D_ / 128, MTOT / 128), 256, GSMEM_BYTES>>>(
        ctx, woutt, bout, out, D_, 0);
}